// round 8
// baseline (speedup 1.0000x reference)
#include <cuda_runtime.h>
#include <cuda_bf16.h>
#include <math.h>
#include <stdint.h>

// Problem: B=4, T=2048, D=2048, HEADS=16
// Chain:
//   K1: kv = x(8192x2048) @ w_qk^T(4096x2048)      -> g_kv fp32
//   prep: kt=k0^T, v, vt=v^T  (bf16 hi/lo splits, K-major rows of 2048)
//   K2: s[b,i,j] = scale * kt[i,:] . v[j,:]        -> g_s fp32
//   K3: row softmax of s -> bf16 hi/lo splits (a)
//   K4: q = a @ vt^T                                -> g_q fp32
//   prep: qg[r] = q[gather(r)] bf16 splits
//   K5: out = qg @ w_dense^T + bias
//
// GEMM engine: mma.sync m16n8k16 bf16, 2-way bf16 split, 3 products (hh,hl,lh).
// R7: block tile 128x256, warp tile 64x64 (6:1 HMMA:LDSM), GBK=32, 3-stage
// cp.async ring, one __syncthreads per stage, product-staged register reuse.

// ---------------------------------------------------------------- scratch ---
static __device__ float g_kv[33554432];   // 4*2048*4096
static __device__ float g_s [16777216];   // 4*2048*2048
static __device__ float g_q [16777216];   // 4*2048*2048

static __device__ __nv_bfloat16 g_xh[16777216],  g_xl[16777216];
static __device__ __nv_bfloat16 g_wqh[8388608],  g_wql[8388608];
static __device__ __nv_bfloat16 g_wdh[4194304],  g_wdl[4194304];
static __device__ __nv_bfloat16 g_kth[16777216], g_ktl[16777216];
static __device__ __nv_bfloat16 g_vh [16777216], g_vl [16777216];
static __device__ __nv_bfloat16 g_vth[16777216], g_vtl[16777216];
static __device__ __nv_bfloat16 g_ah [16777216], g_al [16777216];
static __device__ __nv_bfloat16 g_qgh[16777216], g_qgl[16777216];

// --------------------------------------------------------------- helpers ---
__device__ __forceinline__ uint32_t smem_u32(const void* p) {
    uint32_t a;
    asm("{ .reg .u64 t; cvta.to.shared.u64 t, %1; cvt.u32.u64 %0, t; }"
        : "=r"(a) : "l"(p));
    return a;
}
__device__ __forceinline__ void cp16(uint32_t dst, const void* src) {
    asm volatile("cp.async.cg.shared.global [%0], [%1], 16;"
                 :: "r"(dst), "l"(src) : "memory");
}
#define CP_COMMIT() asm volatile("cp.async.commit_group;" ::: "memory")
#define CP_WAIT1()  asm volatile("cp.async.wait_group 1;" ::: "memory")

__device__ __forceinline__ void ldsm4(uint32_t* r, uint32_t addr) {
    asm volatile("ldmatrix.sync.aligned.m8n8.x4.shared.b16 {%0,%1,%2,%3}, [%4];"
                 : "=r"(r[0]), "=r"(r[1]), "=r"(r[2]), "=r"(r[3]) : "r"(addr));
}
__device__ __forceinline__ void mma16816(float* c, const uint32_t* a, const uint32_t* b) {
    asm volatile(
        "mma.sync.aligned.m16n8k16.row.col.f32.bf16.bf16.f32 "
        "{%0,%1,%2,%3}, {%4,%5,%6,%7}, {%8,%9}, {%0,%1,%2,%3};"
        : "+f"(c[0]), "+f"(c[1]), "+f"(c[2]), "+f"(c[3])
        : "r"(a[0]), "r"(a[1]), "r"(a[2]), "r"(a[3]), "r"(b[0]), "r"(b[1]));
}

__device__ __forceinline__ void split1(float x, __nv_bfloat16& h, __nv_bfloat16& l) {
    h = __float2bfloat16(x);
    l = __float2bfloat16(x - __bfloat162float(h));
}
__device__ __forceinline__ size_t gather_row_off(int r) {
    int vh = r >> 6;
    int b  = (r >> 4) & 3;
    int h  = r & 15;
    return ((size_t)b * 2048 + (size_t)h * 128 + (size_t)vh) * 2048;
}

// ------------------------------------------------------------ bf16 GEMM ----
// C(m,n) = alpha*sum_k (Ah+Al)(m,k)*(Bh+Bl)(n,k) [+bias(n)], drop Al*Bl.
// Operands K-major bf16, row length 2048, K=2048.
// Block 128x256, k-depth 32/stage, 8 warps (2x4), warp tile 64x64.
#define GK       2048
#define GBK      32
#define NCHUNK   (GK / GBK)        // 64
#define ROWB     80u               // 32 bf16 = 64B data + 16B pad
#define AT_B     (128u * ROWB)     // 10240 (A tile: 128 rows)
#define BT_B     (256u * ROWB)     // 20480 (B tile: 256 rows)
#define OFF_AH   0u
#define OFF_AL   AT_B
#define OFF_BH   (2u * AT_B)
#define OFF_BL   (2u * AT_B + BT_B)
#define STAGE_B  (2u * AT_B + 2u * BT_B)   // 61440
#define GEMM_SMEM (3u * STAGE_B)           // 184320

__global__ __launch_bounds__(256, 1)
void gemm_mma(const __nv_bfloat16* __restrict__ Ah, const __nv_bfloat16* __restrict__ Al,
              size_t strideA,
              const __nv_bfloat16* __restrict__ Bh, const __nv_bfloat16* __restrict__ Bl,
              size_t strideB,
              float* __restrict__ C, int ldc, size_t strideC,
              float alpha, const float* __restrict__ bias)
{
    extern __shared__ char smem[];
    const uint32_t sbase = smem_u32(smem);

    const int tid  = threadIdx.x;
    const int lane = tid & 31;
    const int wid  = tid >> 5;
    const int wm0  = (wid & 1) * 64;    // warp M offset in tile
    const int wn0  = (wid >> 1) * 64;   // warp N offset in tile

    Ah += blockIdx.z * strideA;  Al += blockIdx.z * strideA;
    Bh += blockIdx.z * strideB;  Bl += blockIdx.z * strideB;
    C  += blockIdx.z * strideC;
    const int m0 = blockIdx.y * 128;
    const int n0 = blockIdx.x * 256;

    // loader: 4 x 16B chunks per 64B row; lr = row 0..63
    const int lc = tid & 3;
    const int lr = tid >> 2;

    auto load_stage = [&](int t) {
        if (t < NCHUNK) {
            const uint32_t sb = sbase + (uint32_t)(t % 3) * STAGE_B;
            const int ks = t * GBK;
#pragma unroll
            for (int i = 0; i < 2; i++) {               // A: 128 rows
                const int row = lr + i * 64;
                const uint32_t d = (uint32_t)row * ROWB + lc * 16;
                const size_t aoff = (size_t)(m0 + row) * GK + ks + lc * 8;
                cp16(sb + OFF_AH + d, Ah + aoff);
                cp16(sb + OFF_AL + d, Al + aoff);
            }
#pragma unroll
            for (int i = 0; i < 4; i++) {               // B: 256 rows
                const int row = lr + i * 64;
                const uint32_t d = (uint32_t)row * ROWB + lc * 16;
                const size_t boff = (size_t)(n0 + row) * GK + ks + lc * 8;
                cp16(sb + OFF_BH + d, Bh + boff);
                cp16(sb + OFF_BL + d, Bl + boff);
            }
        }
        CP_COMMIT();
    };

    float acc[4][8][4];
#pragma unroll
    for (int i = 0; i < 4; i++)
#pragma unroll
        for (int j = 0; j < 8; j++)
#pragma unroll
            for (int k = 0; k < 4; k++) acc[i][j][k] = 0.f;

    // ldmatrix lane-base offsets within a stage
    const uint32_t a_lbase = (uint32_t)(wm0 + (lane & 15)) * ROWB + (uint32_t)(lane >> 4) * 16;
    const uint32_t b_lbase = (uint32_t)(wn0 + ((lane >> 4) & 1) * 8 + (lane & 7)) * ROWB
                           + (uint32_t)((lane >> 3) & 1) * 16;

    load_stage(0);
    load_stage(1);

    for (int t = 0; t < NCHUNK; t++) {
        CP_WAIT1();                 // stage t landed
        __syncthreads();            // slot (t-1)%3 reads finished
        load_stage(t + 2);          // fill slot (t+2)%3 == (t-1)%3

        const uint32_t sb = sbase + (uint32_t)(t % 3) * STAGE_B;
#pragma unroll
        for (int k16 = 0; k16 < 2; k16++) {
            const uint32_t kb = (uint32_t)k16 * 32;   // 16 bf16 = 32B
            // --- product 1: Ah * Bh ---
            uint32_t ah[4][4], bh[4][4];
#pragma unroll
            for (int mt = 0; mt < 4; mt++)
                ldsm4(ah[mt], sb + OFF_AH + a_lbase + (uint32_t)mt * (16u * ROWB) + kb);
#pragma unroll
            for (int p = 0; p < 4; p++)
                ldsm4(bh[p], sb + OFF_BH + b_lbase + (uint32_t)p * (16u * ROWB) + kb);
#pragma unroll
            for (int mt = 0; mt < 4; mt++)
#pragma unroll
                for (int p = 0; p < 4; p++) {
                    mma16816(acc[mt][2 * p + 0], ah[mt], &bh[p][0]);
                    mma16816(acc[mt][2 * p + 1], ah[mt], &bh[p][2]);
                }
            // --- product 2: Ah * Bl (bl short-lived) ---
            {
                uint32_t bl[4][4];
#pragma unroll
                for (int p = 0; p < 4; p++)
                    ldsm4(bl[p], sb + OFF_BL + b_lbase + (uint32_t)p * (16u * ROWB) + kb);
#pragma unroll
                for (int mt = 0; mt < 4; mt++)
#pragma unroll
                    for (int p = 0; p < 4; p++) {
                        mma16816(acc[mt][2 * p + 0], ah[mt], &bl[p][0]);
                        mma16816(acc[mt][2 * p + 1], ah[mt], &bl[p][2]);
                    }
            }
            // --- product 3: Al * Bh (al short-lived) ---
            {
                uint32_t al[4][4];
#pragma unroll
                for (int mt = 0; mt < 4; mt++)
                    ldsm4(al[mt], sb + OFF_AL + a_lbase + (uint32_t)mt * (16u * ROWB) + kb);
#pragma unroll
                for (int mt = 0; mt < 4; mt++)
#pragma unroll
                    for (int p = 0; p < 4; p++) {
                        mma16816(acc[mt][2 * p + 0], al[mt], &bh[p][0]);
                        mma16816(acc[mt][2 * p + 1], al[mt], &bh[p][2]);
                    }
            }
        }
    }

    // ---- epilogue: direct fp32 stores ----
    const int er = lane >> 2;          // row group 0..7
    const int ec = (lane & 3) * 2;     // col pair
#pragma unroll
    for (int mt = 0; mt < 4; mt++) {
#pragma unroll
        for (int nt = 0; nt < 8; nt++) {
            int m = m0 + wm0 + mt * 16 + er;
            int n = n0 + wn0 + nt * 8 + ec;
            float b0 = 0.f, b1 = 0.f;
            if (bias) { b0 = __ldg(bias + n); b1 = __ldg(bias + n + 1); }
            float2 v0, v1;
            v0.x = alpha * acc[mt][nt][0] + b0;
            v0.y = alpha * acc[mt][nt][1] + b1;
            v1.x = alpha * acc[mt][nt][2] + b0;
            v1.y = alpha * acc[mt][nt][3] + b1;
            *(float2*)&C[(size_t)m * (size_t)ldc + n]       = v0;
            *(float2*)&C[(size_t)(m + 8) * (size_t)ldc + n] = v1;
        }
    }
}

// ----------------------------------------------------------- prep kernels ---
__global__ __launch_bounds__(256)
void copy_split_k(const float* __restrict__ src, size_t src_rstride, size_t src_bstride,
                  __nv_bfloat16* __restrict__ dh, __nv_bfloat16* __restrict__ dl,
                  size_t dst_bstride)
{
    size_t row = blockIdx.y;
    size_t col = (size_t)blockIdx.x * 1024 + threadIdx.x * 4;
    float4 v = *(const float4*)(src + (size_t)blockIdx.z * src_bstride + row * src_rstride + col);
    __nv_bfloat16 h0, h1, h2, h3, l0, l1, l2, l3;
    split1(v.x, h0, l0); split1(v.y, h1, l1);
    split1(v.z, h2, l2); split1(v.w, h3, l3);
    size_t o = (size_t)blockIdx.z * dst_bstride + row * 2048 + col;
    ((__nv_bfloat162*)(dh + o))[0] = __halves2bfloat162(h0, h1);
    ((__nv_bfloat162*)(dh + o))[1] = __halves2bfloat162(h2, h3);
    ((__nv_bfloat162*)(dl + o))[0] = __halves2bfloat162(l0, l1);
    ((__nv_bfloat162*)(dl + o))[1] = __halves2bfloat162(l2, l3);
}

__global__ __launch_bounds__(256)
void transpose_split_k(const float* __restrict__ src, size_t src_bstride, int src_ld,
                       __nv_bfloat16* __restrict__ dh, __nv_bfloat16* __restrict__ dl,
                       size_t dst_bstride)
{
    __shared__ float tile[32][33];
    int tx = threadIdx.x, ty = threadIdx.y;      // blockDim (32, 8)
    int i0 = blockIdx.x * 32, m0 = blockIdx.y * 32;
    const float* s = src + (size_t)blockIdx.z * src_bstride;
#pragma unroll
    for (int r = 0; r < 4; r++)
        tile[ty + r * 8][tx] = s[(size_t)(m0 + ty + r * 8) * src_ld + i0 + tx];
    __syncthreads();
#pragma unroll
    for (int r = 0; r < 4; r++) {
        float x = tile[tx][ty + r * 8];
        __nv_bfloat16 h, l; split1(x, h, l);
        size_t o = (size_t)blockIdx.z * dst_bstride +
                   (size_t)(i0 + ty + r * 8) * 2048 + m0 + tx;
        dh[o] = h; dl[o] = l;
    }
}

__global__ __launch_bounds__(256)
void softmax_split_k(const float* __restrict__ s,
                     __nv_bfloat16* __restrict__ ah, __nv_bfloat16* __restrict__ al)
{
    const float* p = s + (size_t)blockIdx.x * 2048;
    int tid = threadIdx.x, warp = tid >> 5, lane = tid & 31;
    __shared__ float red[8];

    float4 v0 = *(const float4*)(p + tid * 4);
    float4 v1 = *(const float4*)(p + 1024 + tid * 4);

    float m = fmaxf(fmaxf(fmaxf(v0.x, v0.y), fmaxf(v0.z, v0.w)),
                    fmaxf(fmaxf(v1.x, v1.y), fmaxf(v1.z, v1.w)));
#pragma unroll
    for (int o = 16; o > 0; o >>= 1) m = fmaxf(m, __shfl_xor_sync(0xffffffffu, m, o));
    if (lane == 0) red[warp] = m;
    __syncthreads();
    float bm = red[0];
#pragma unroll
    for (int i = 1; i < 8; i++) bm = fmaxf(bm, red[i]);
    __syncthreads();

    v0.x = __expf(v0.x - bm); v0.y = __expf(v0.y - bm);
    v0.z = __expf(v0.z - bm); v0.w = __expf(v0.w - bm);
    v1.x = __expf(v1.x - bm); v1.y = __expf(v1.y - bm);
    v1.z = __expf(v1.z - bm); v1.w = __expf(v1.w - bm);

    float sm = v0.x + v0.y + v0.z + v0.w + v1.x + v1.y + v1.z + v1.w;
#pragma unroll
    for (int o = 16; o > 0; o >>= 1) sm += __shfl_xor_sync(0xffffffffu, sm, o);
    if (lane == 0) red[warp] = sm;
    __syncthreads();
    float tot = red[0];
#pragma unroll
    for (int i = 1; i < 8; i++) tot += red[i];
    float inv = 1.f / tot;

    size_t base = (size_t)blockIdx.x * 2048;
    float vals[8] = {v0.x * inv, v0.y * inv, v0.z * inv, v0.w * inv,
                     v1.x * inv, v1.y * inv, v1.z * inv, v1.w * inv};
    size_t offs[2] = {base + tid * 4, base + 1024 + tid * 4};
#pragma unroll
    for (int half = 0; half < 2; half++) {
        __nv_bfloat16 h0, h1, h2, h3, l0, l1, l2, l3;
        split1(vals[half * 4 + 0], h0, l0); split1(vals[half * 4 + 1], h1, l1);
        split1(vals[half * 4 + 2], h2, l2); split1(vals[half * 4 + 3], h3, l3);
        size_t o = offs[half];
        ((__nv_bfloat162*)(ah + o))[0] = __halves2bfloat162(h0, h1);
        ((__nv_bfloat162*)(ah + o))[1] = __halves2bfloat162(h2, h3);
        ((__nv_bfloat162*)(al + o))[0] = __halves2bfloat162(l0, l1);
        ((__nv_bfloat162*)(al + o))[1] = __halves2bfloat162(l2, l3);
    }
}

__global__ __launch_bounds__(256)
void gather_split_k(const float* __restrict__ q,
                    __nv_bfloat16* __restrict__ dh, __nv_bfloat16* __restrict__ dl)
{
    int r = blockIdx.y;
    size_t col = (size_t)blockIdx.x * 1024 + threadIdx.x * 4;
    float4 v = *(const float4*)(q + gather_row_off(r) + col);
    __nv_bfloat16 h0, h1, h2, h3, l0, l1, l2, l3;
    split1(v.x, h0, l0); split1(v.y, h1, l1);
    split1(v.z, h2, l2); split1(v.w, h3, l3);
    size_t o = (size_t)r * 2048 + col;
    ((__nv_bfloat162*)(dh + o))[0] = __halves2bfloat162(h0, h1);
    ((__nv_bfloat162*)(dh + o))[1] = __halves2bfloat162(h2, h3);
    ((__nv_bfloat162*)(dl + o))[0] = __halves2bfloat162(l0, l1);
    ((__nv_bfloat162*)(dl + o))[1] = __halves2bfloat162(l2, l3);
}

// ------------------------------------------------------------------ driver ---
extern "C" void kernel_launch(void* const* d_in, const int* in_sizes, int n_in,
                              void* d_out, int out_size)
{
    const float* x       = (const float*)d_in[0];
    const float* w_qk    = (const float*)d_in[1];
    const float* w_dense = (const float*)d_in[2];
    const float* b_dense = (const float*)d_in[3];
    float* out = (float*)d_out;

    float *kv, *s, *q;
    cudaGetSymbolAddress((void**)&kv, g_kv);
    cudaGetSymbolAddress((void**)&s,  g_s);
    cudaGetSymbolAddress((void**)&q,  g_q);
    __nv_bfloat16 *xh, *xl, *wqh, *wql, *wdh, *wdl, *kth, *ktl, *vh, *vl,
                  *vth, *vtl, *ah, *al, *qgh, *qgl;
    cudaGetSymbolAddress((void**)&xh,  g_xh);  cudaGetSymbolAddress((void**)&xl,  g_xl);
    cudaGetSymbolAddress((void**)&wqh, g_wqh); cudaGetSymbolAddress((void**)&wql, g_wql);
    cudaGetSymbolAddress((void**)&wdh, g_wdh); cudaGetSymbolAddress((void**)&wdl, g_wdl);
    cudaGetSymbolAddress((void**)&kth, g_kth); cudaGetSymbolAddress((void**)&ktl, g_ktl);
    cudaGetSymbolAddress((void**)&vh,  g_vh);  cudaGetSymbolAddress((void**)&vl,  g_vl);
    cudaGetSymbolAddress((void**)&vth, g_vth); cudaGetSymbolAddress((void**)&vtl, g_vtl);
    cudaGetSymbolAddress((void**)&ah,  g_ah);  cudaGetSymbolAddress((void**)&al,  g_al);
    cudaGetSymbolAddress((void**)&qgh, g_qgh); cudaGetSymbolAddress((void**)&qgl, g_qgl);

    cudaFuncSetAttribute(gemm_mma, cudaFuncAttributeMaxDynamicSharedMemorySize, GEMM_SMEM);

    const float scale = (float)(1.0 / sqrt(2048.0 * 2047.0 / 2.0));
    const size_t sKV = 2048ull * 4096ull;
    const size_t sSQ = 2048ull * 2048ull;

    // splits of the raw inputs
    copy_split_k<<<dim3(2, 8192, 1), 256>>>(x,       2048, 0, xh,  xl,  0);
    copy_split_k<<<dim3(2, 4096, 1), 256>>>(w_qk,    2048, 0, wqh, wql, 0);
    copy_split_k<<<dim3(2, 2048, 1), 256>>>(w_dense, 2048, 0, wdh, wdl, 0);

    // K1: kv = x @ w_qk^T   M=8192 N=4096 K=2048
    gemm_mma<<<dim3(16, 64, 1), 256, GEMM_SMEM>>>(
        xh, xl, 0, wqh, wql, 0, kv, 4096, 0, 1.f, nullptr);

    // kv -> kt (k0^T), v (copy), vt (v^T), all bf16 splits
    transpose_split_k<<<dim3(64, 64, 4), dim3(32, 8)>>>(kv,        sKV, 4096, kth, ktl, sSQ);
    copy_split_k     <<<dim3(2, 2048, 4), 256>>>      (kv + 2048, 4096, sKV, vh,  vl,  sSQ);
    transpose_split_k<<<dim3(64, 64, 4), dim3(32, 8)>>>(kv + 2048, sKV, 4096, vth, vtl, sSQ);

    // K2: s = scale * kt @ v^T (per batch)
    gemm_mma<<<dim3(8, 16, 4), 256, GEMM_SMEM>>>(
        kth, ktl, sSQ, vh, vl, sSQ, s, 2048, sSQ, scale, nullptr);

    // K3: softmax rows -> bf16 splits
    softmax_split_k<<<8192, 256>>>(s, ah, al);

    // K4: q = a @ vt^T (per batch)
    gemm_mma<<<dim3(8, 16, 4), 256, GEMM_SMEM>>>(
        ah, al, sSQ, vth, vtl, sSQ, q, 2048, sSQ, 1.f, nullptr);

    // gather + split q rows
    gather_split_k<<<dim3(2, 8192, 1), 256>>>(q, qgh, qgl);

    // K5: out = qg @ w_dense^T + bias   M=8192 N=2048 K=2048
    gemm_mma<<<dim3(8, 64, 1), 256, GEMM_SMEM>>>(
        qgh, qgl, 0, wdh, wdl, 0, out, 2048, 0, 1.f, b_dense);
}

// round 9
// speedup vs baseline: 1.1495x; 1.1495x over previous
#include <cuda_runtime.h>
#include <cuda_bf16.h>
#include <math.h>
#include <stdint.h>

// Problem: B=4, T=2048, D=2048, HEADS=16
// Chain:
//   K1: kv = x(8192x2048) @ w_qk^T(4096x2048)      -> g_kv fp32
//   prep: kt=k0^T, v, vt=v^T  (bf16 hi/lo splits, K-major rows of 2048)
//   K2: s[b,i,j] = scale * kt[i,:] . v[j,:]        -> g_s fp32
//   K3: row softmax of s -> bf16 hi/lo splits (a)
//   K4: q = a @ vt^T                                -> g_q fp32
//   prep: qg[r] = q[gather(r)] bf16 splits
//   K5: out = qg @ w_dense^T + bias
//
// GEMM engine: mma.sync m16n8k16 bf16, 2-way bf16 split, 3 products (hh,hl,lh).
// R9: back to 128x128 / warp 64x32 (R6 winner), but 2 CTAs/SM:
//     GBK=32, 2-stage 80KB ring, launch_bounds(256,2) (<=128 regs),
//     product-staged fragments, exact tail wait.

// ---------------------------------------------------------------- scratch ---
static __device__ float g_kv[33554432];   // 4*2048*4096
static __device__ float g_s [16777216];   // 4*2048*2048
static __device__ float g_q [16777216];   // 4*2048*2048

static __device__ __nv_bfloat16 g_xh[16777216],  g_xl[16777216];
static __device__ __nv_bfloat16 g_wqh[8388608],  g_wql[8388608];
static __device__ __nv_bfloat16 g_wdh[4194304],  g_wdl[4194304];
static __device__ __nv_bfloat16 g_kth[16777216], g_ktl[16777216];
static __device__ __nv_bfloat16 g_vh [16777216], g_vl [16777216];
static __device__ __nv_bfloat16 g_vth[16777216], g_vtl[16777216];
static __device__ __nv_bfloat16 g_ah [16777216], g_al [16777216];
static __device__ __nv_bfloat16 g_qgh[16777216], g_qgl[16777216];

// --------------------------------------------------------------- helpers ---
__device__ __forceinline__ uint32_t smem_u32(const void* p) {
    uint32_t a;
    asm("{ .reg .u64 t; cvta.to.shared.u64 t, %1; cvt.u32.u64 %0, t; }"
        : "=r"(a) : "l"(p));
    return a;
}
__device__ __forceinline__ void cp16(uint32_t dst, const void* src) {
    asm volatile("cp.async.cg.shared.global [%0], [%1], 16;"
                 :: "r"(dst), "l"(src) : "memory");
}
#define CP_COMMIT() asm volatile("cp.async.commit_group;" ::: "memory")
#define CP_WAIT1()  asm volatile("cp.async.wait_group 1;" ::: "memory")
#define CP_WAIT0()  asm volatile("cp.async.wait_group 0;" ::: "memory")

__device__ __forceinline__ void ldsm4(uint32_t* r, uint32_t addr) {
    asm volatile("ldmatrix.sync.aligned.m8n8.x4.shared.b16 {%0,%1,%2,%3}, [%4];"
                 : "=r"(r[0]), "=r"(r[1]), "=r"(r[2]), "=r"(r[3]) : "r"(addr));
}
__device__ __forceinline__ void mma16816(float* c, const uint32_t* a, const uint32_t* b) {
    asm volatile(
        "mma.sync.aligned.m16n8k16.row.col.f32.bf16.bf16.f32 "
        "{%0,%1,%2,%3}, {%4,%5,%6,%7}, {%8,%9}, {%0,%1,%2,%3};"
        : "+f"(c[0]), "+f"(c[1]), "+f"(c[2]), "+f"(c[3])
        : "r"(a[0]), "r"(a[1]), "r"(a[2]), "r"(a[3]), "r"(b[0]), "r"(b[1]));
}

__device__ __forceinline__ void split1(float x, __nv_bfloat16& h, __nv_bfloat16& l) {
    h = __float2bfloat16(x);
    l = __float2bfloat16(x - __bfloat162float(h));
}
__device__ __forceinline__ size_t gather_row_off(int r) {
    int vh = r >> 6;
    int b  = (r >> 4) & 3;
    int h  = r & 15;
    return ((size_t)b * 2048 + (size_t)h * 128 + (size_t)vh) * 2048;
}

// ------------------------------------------------------------ bf16 GEMM ----
// C(m,n) = alpha*sum_k (Ah+Al)(m,k)*(Bh+Bl)(n,k) [+bias(n)], drop Al*Bl.
// Operands K-major bf16, row length 2048, K=2048.
// Block 128x128, k-depth 32/stage, 8 warps (2x4), warp tile 64x32.
// 2-stage cp.async double buffer; 2 CTAs/SM.
#define GK       2048
#define GBK      32
#define NCHUNK   (GK / GBK)        // 64
#define ROWB     80u               // 32 bf16 = 64B data + 16B pad (ldmatrix conflict-free)
#define TILE_B   (128u * ROWB)     // 10240
#define OFF_AH   0u
#define OFF_AL   TILE_B
#define OFF_BH   (2u * TILE_B)
#define OFF_BL   (3u * TILE_B)
#define STAGE_B  (4u * TILE_B)     // 40960
#define GEMM_SMEM (2u * STAGE_B)   // 81920 -> 2 CTAs/SM

__global__ __launch_bounds__(256, 2)
void gemm_mma(const __nv_bfloat16* __restrict__ Ah, const __nv_bfloat16* __restrict__ Al,
              size_t strideA,
              const __nv_bfloat16* __restrict__ Bh, const __nv_bfloat16* __restrict__ Bl,
              size_t strideB,
              float* __restrict__ C, int ldc, size_t strideC,
              float alpha, const float* __restrict__ bias)
{
    extern __shared__ char smem[];
    const uint32_t sbase = smem_u32(smem);

    const int tid  = threadIdx.x;
    const int lane = tid & 31;
    const int wid  = tid >> 5;
    const int wm0  = (wid & 1) * 64;    // warp M offset in tile
    const int wn0  = (wid >> 1) * 32;   // warp N offset in tile

    Ah += blockIdx.z * strideA;  Al += blockIdx.z * strideA;
    Bh += blockIdx.z * strideB;  Bl += blockIdx.z * strideB;
    C  += blockIdx.z * strideC;
    const int m0 = blockIdx.y * 128;
    const int n0 = blockIdx.x * 128;

    // loader: per 64B row, 4 x 16B chunks; lr = row 0..63 (x2), lc = chunk
    const int lc = tid & 3;
    const int lr = tid >> 2;

    auto load_stage = [&](int t) {
        if (t < NCHUNK) {
            const uint32_t sb = sbase + (uint32_t)(t & 1) * STAGE_B;
            const int ks = t * GBK;
#pragma unroll
            for (int i = 0; i < 2; i++) {
                const int row = lr + i * 64;
                const uint32_t d = (uint32_t)row * ROWB + lc * 16;
                const size_t aoff = (size_t)(m0 + row) * GK + ks + lc * 8;
                const size_t boff = (size_t)(n0 + row) * GK + ks + lc * 8;
                cp16(sb + OFF_AH + d, Ah + aoff);
                cp16(sb + OFF_AL + d, Al + aoff);
                cp16(sb + OFF_BH + d, Bh + boff);
                cp16(sb + OFF_BL + d, Bl + boff);
            }
        }
        CP_COMMIT();
    };

    float acc[4][4][4];
#pragma unroll
    for (int i = 0; i < 4; i++)
#pragma unroll
        for (int j = 0; j < 4; j++)
#pragma unroll
            for (int k = 0; k < 4; k++) acc[i][j][k] = 0.f;

    // ldmatrix lane-base offsets within a stage
    const uint32_t a_lbase = (uint32_t)(wm0 + (lane & 15)) * ROWB + (uint32_t)(lane >> 4) * 16;
    const uint32_t b_lbase = (uint32_t)(wn0 + ((lane >> 4) & 1) * 8 + (lane & 7)) * ROWB
                           + (uint32_t)((lane >> 3) & 1) * 16;

    load_stage(0);
    load_stage(1);

    for (int t = 0; t < NCHUNK; t++) {
        if (t + 1 < NCHUNK) { CP_WAIT1(); } else { CP_WAIT0(); }  // stage t landed
        __syncthreads();

        const uint32_t sb = sbase + (uint32_t)(t & 1) * STAGE_B;
#pragma unroll
        for (int k16 = 0; k16 < 2; k16++) {
            const uint32_t kb = (uint32_t)k16 * 32;   // 16 bf16 = 32B
            // --- product 1: Ah * Bh ---
            uint32_t ah[4][4], bh[2][4];
#pragma unroll
            for (int mt = 0; mt < 4; mt++)
                ldsm4(ah[mt], sb + OFF_AH + a_lbase + (uint32_t)mt * (16u * ROWB) + kb);
#pragma unroll
            for (int p = 0; p < 2; p++)
                ldsm4(bh[p], sb + OFF_BH + b_lbase + (uint32_t)p * (16u * ROWB) + kb);
#pragma unroll
            for (int mt = 0; mt < 4; mt++)
#pragma unroll
                for (int p = 0; p < 2; p++) {
                    mma16816(acc[mt][2 * p + 0], ah[mt], &bh[p][0]);
                    mma16816(acc[mt][2 * p + 1], ah[mt], &bh[p][2]);
                }
            // --- product 2: Ah * Bl (bl short-lived) ---
            {
                uint32_t bl[2][4];
#pragma unroll
                for (int p = 0; p < 2; p++)
                    ldsm4(bl[p], sb + OFF_BL + b_lbase + (uint32_t)p * (16u * ROWB) + kb);
#pragma unroll
                for (int mt = 0; mt < 4; mt++)
#pragma unroll
                    for (int p = 0; p < 2; p++) {
                        mma16816(acc[mt][2 * p + 0], ah[mt], &bl[p][0]);
                        mma16816(acc[mt][2 * p + 1], ah[mt], &bl[p][2]);
                    }
            }
            // --- product 3: Al * Bh (al short-lived, ah dead) ---
            {
                uint32_t al[4][4];
#pragma unroll
                for (int mt = 0; mt < 4; mt++)
                    ldsm4(al[mt], sb + OFF_AL + a_lbase + (uint32_t)mt * (16u * ROWB) + kb);
#pragma unroll
                for (int mt = 0; mt < 4; mt++)
#pragma unroll
                    for (int p = 0; p < 2; p++) {
                        mma16816(acc[mt][2 * p + 0], al[mt], &bh[p][0]);
                        mma16816(acc[mt][2 * p + 1], al[mt], &bh[p][2]);
                    }
            }
        }
        __syncthreads();            // all reads of buf t done before refill
        load_stage(t + 2);          // into buf t&1
    }

    // ---- epilogue: direct fp32 stores ----
    const int er = lane >> 2;          // row group 0..7
    const int ec = (lane & 3) * 2;     // col pair
#pragma unroll
    for (int mt = 0; mt < 4; mt++) {
#pragma unroll
        for (int nt = 0; nt < 4; nt++) {
            int m = m0 + wm0 + mt * 16 + er;
            int n = n0 + wn0 + nt * 8 + ec;
            float b0 = 0.f, b1 = 0.f;
            if (bias) { b0 = __ldg(bias + n); b1 = __ldg(bias + n + 1); }
            float2 v0, v1;
            v0.x = alpha * acc[mt][nt][0] + b0;
            v0.y = alpha * acc[mt][nt][1] + b1;
            v1.x = alpha * acc[mt][nt][2] + b0;
            v1.y = alpha * acc[mt][nt][3] + b1;
            *(float2*)&C[(size_t)m * (size_t)ldc + n]       = v0;
            *(float2*)&C[(size_t)(m + 8) * (size_t)ldc + n] = v1;
        }
    }
}

// ----------------------------------------------------------- prep kernels ---
__global__ __launch_bounds__(256)
void copy_split_k(const float* __restrict__ src, size_t src_rstride, size_t src_bstride,
                  __nv_bfloat16* __restrict__ dh, __nv_bfloat16* __restrict__ dl,
                  size_t dst_bstride)
{
    size_t row = blockIdx.y;
    size_t col = (size_t)blockIdx.x * 1024 + threadIdx.x * 4;
    float4 v = *(const float4*)(src + (size_t)blockIdx.z * src_bstride + row * src_rstride + col);
    __nv_bfloat16 h0, h1, h2, h3, l0, l1, l2, l3;
    split1(v.x, h0, l0); split1(v.y, h1, l1);
    split1(v.z, h2, l2); split1(v.w, h3, l3);
    size_t o = (size_t)blockIdx.z * dst_bstride + row * 2048 + col;
    ((__nv_bfloat162*)(dh + o))[0] = __halves2bfloat162(h0, h1);
    ((__nv_bfloat162*)(dh + o))[1] = __halves2bfloat162(h2, h3);
    ((__nv_bfloat162*)(dl + o))[0] = __halves2bfloat162(l0, l1);
    ((__nv_bfloat162*)(dl + o))[1] = __halves2bfloat162(l2, l3);
}

__global__ __launch_bounds__(256)
void transpose_split_k(const float* __restrict__ src, size_t src_bstride, int src_ld,
                       __nv_bfloat16* __restrict__ dh, __nv_bfloat16* __restrict__ dl,
                       size_t dst_bstride)
{
    __shared__ float tile[32][33];
    int tx = threadIdx.x, ty = threadIdx.y;      // blockDim (32, 8)
    int i0 = blockIdx.x * 32, m0 = blockIdx.y * 32;
    const float* s = src + (size_t)blockIdx.z * src_bstride;
#pragma unroll
    for (int r = 0; r < 4; r++)
        tile[ty + r * 8][tx] = s[(size_t)(m0 + ty + r * 8) * src_ld + i0 + tx];
    __syncthreads();
#pragma unroll
    for (int r = 0; r < 4; r++) {
        float x = tile[tx][ty + r * 8];
        __nv_bfloat16 h, l; split1(x, h, l);
        size_t o = (size_t)blockIdx.z * dst_bstride +
                   (size_t)(i0 + ty + r * 8) * 2048 + m0 + tx;
        dh[o] = h; dl[o] = l;
    }
}

__global__ __launch_bounds__(256)
void softmax_split_k(const float* __restrict__ s,
                     __nv_bfloat16* __restrict__ ah, __nv_bfloat16* __restrict__ al)
{
    const float* p = s + (size_t)blockIdx.x * 2048;
    int tid = threadIdx.x, warp = tid >> 5, lane = tid & 31;
    __shared__ float red[8];

    float4 v0 = *(const float4*)(p + tid * 4);
    float4 v1 = *(const float4*)(p + 1024 + tid * 4);

    float m = fmaxf(fmaxf(fmaxf(v0.x, v0.y), fmaxf(v0.z, v0.w)),
                    fmaxf(fmaxf(v1.x, v1.y), fmaxf(v1.z, v1.w)));
#pragma unroll
    for (int o = 16; o > 0; o >>= 1) m = fmaxf(m, __shfl_xor_sync(0xffffffffu, m, o));
    if (lane == 0) red[warp] = m;
    __syncthreads();
    float bm = red[0];
#pragma unroll
    for (int i = 1; i < 8; i++) bm = fmaxf(bm, red[i]);
    __syncthreads();

    v0.x = __expf(v0.x - bm); v0.y = __expf(v0.y - bm);
    v0.z = __expf(v0.z - bm); v0.w = __expf(v0.w - bm);
    v1.x = __expf(v1.x - bm); v1.y = __expf(v1.y - bm);
    v1.z = __expf(v1.z - bm); v1.w = __expf(v1.w - bm);

    float sm = v0.x + v0.y + v0.z + v0.w + v1.x + v1.y + v1.z + v1.w;
#pragma unroll
    for (int o = 16; o > 0; o >>= 1) sm += __shfl_xor_sync(0xffffffffu, sm, o);
    if (lane == 0) red[warp] = sm;
    __syncthreads();
    float tot = red[0];
#pragma unroll
    for (int i = 1; i < 8; i++) tot += red[i];
    float inv = 1.f / tot;

    size_t base = (size_t)blockIdx.x * 2048;
    float vals[8] = {v0.x * inv, v0.y * inv, v0.z * inv, v0.w * inv,
                     v1.x * inv, v1.y * inv, v1.z * inv, v1.w * inv};
    size_t offs[2] = {base + tid * 4, base + 1024 + tid * 4};
#pragma unroll
    for (int half = 0; half < 2; half++) {
        __nv_bfloat16 h0, h1, h2, h3, l0, l1, l2, l3;
        split1(vals[half * 4 + 0], h0, l0); split1(vals[half * 4 + 1], h1, l1);
        split1(vals[half * 4 + 2], h2, l2); split1(vals[half * 4 + 3], h3, l3);
        size_t o = offs[half];
        ((__nv_bfloat162*)(ah + o))[0] = __halves2bfloat162(h0, h1);
        ((__nv_bfloat162*)(ah + o))[1] = __halves2bfloat162(h2, h3);
        ((__nv_bfloat162*)(al + o))[0] = __halves2bfloat162(l0, l1);
        ((__nv_bfloat162*)(al + o))[1] = __halves2bfloat162(l2, l3);
    }
}

__global__ __launch_bounds__(256)
void gather_split_k(const float* __restrict__ q,
                    __nv_bfloat16* __restrict__ dh, __nv_bfloat16* __restrict__ dl)
{
    int r = blockIdx.y;
    size_t col = (size_t)blockIdx.x * 1024 + threadIdx.x * 4;
    float4 v = *(const float4*)(q + gather_row_off(r) + col);
    __nv_bfloat16 h0, h1, h2, h3, l0, l1, l2, l3;
    split1(v.x, h0, l0); split1(v.y, h1, l1);
    split1(v.z, h2, l2); split1(v.w, h3, l3);
    size_t o = (size_t)r * 2048 + col;
    ((__nv_bfloat162*)(dh + o))[0] = __halves2bfloat162(h0, h1);
    ((__nv_bfloat162*)(dh + o))[1] = __halves2bfloat162(h2, h3);
    ((__nv_bfloat162*)(dl + o))[0] = __halves2bfloat162(l0, l1);
    ((__nv_bfloat162*)(dl + o))[1] = __halves2bfloat162(l2, l3);
}

// ------------------------------------------------------------------ driver ---
extern "C" void kernel_launch(void* const* d_in, const int* in_sizes, int n_in,
                              void* d_out, int out_size)
{
    const float* x       = (const float*)d_in[0];
    const float* w_qk    = (const float*)d_in[1];
    const float* w_dense = (const float*)d_in[2];
    const float* b_dense = (const float*)d_in[3];
    float* out = (float*)d_out;

    float *kv, *s, *q;
    cudaGetSymbolAddress((void**)&kv, g_kv);
    cudaGetSymbolAddress((void**)&s,  g_s);
    cudaGetSymbolAddress((void**)&q,  g_q);
    __nv_bfloat16 *xh, *xl, *wqh, *wql, *wdh, *wdl, *kth, *ktl, *vh, *vl,
                  *vth, *vtl, *ah, *al, *qgh, *qgl;
    cudaGetSymbolAddress((void**)&xh,  g_xh);  cudaGetSymbolAddress((void**)&xl,  g_xl);
    cudaGetSymbolAddress((void**)&wqh, g_wqh); cudaGetSymbolAddress((void**)&wql, g_wql);
    cudaGetSymbolAddress((void**)&wdh, g_wdh); cudaGetSymbolAddress((void**)&wdl, g_wdl);
    cudaGetSymbolAddress((void**)&kth, g_kth); cudaGetSymbolAddress((void**)&ktl, g_ktl);
    cudaGetSymbolAddress((void**)&vh,  g_vh);  cudaGetSymbolAddress((void**)&vl,  g_vl);
    cudaGetSymbolAddress((void**)&vth, g_vth); cudaGetSymbolAddress((void**)&vtl, g_vtl);
    cudaGetSymbolAddress((void**)&ah,  g_ah);  cudaGetSymbolAddress((void**)&al,  g_al);
    cudaGetSymbolAddress((void**)&qgh, g_qgh); cudaGetSymbolAddress((void**)&qgl, g_qgl);

    cudaFuncSetAttribute(gemm_mma, cudaFuncAttributeMaxDynamicSharedMemorySize, GEMM_SMEM);

    const float scale = (float)(1.0 / sqrt(2048.0 * 2047.0 / 2.0));
    const size_t sKV = 2048ull * 4096ull;
    const size_t sSQ = 2048ull * 2048ull;

    // splits of the raw inputs
    copy_split_k<<<dim3(2, 8192, 1), 256>>>(x,       2048, 0, xh,  xl,  0);
    copy_split_k<<<dim3(2, 4096, 1), 256>>>(w_qk,    2048, 0, wqh, wql, 0);
    copy_split_k<<<dim3(2, 2048, 1), 256>>>(w_dense, 2048, 0, wdh, wdl, 0);

    // K1: kv = x @ w_qk^T   M=8192 N=4096 K=2048
    gemm_mma<<<dim3(32, 64, 1), 256, GEMM_SMEM>>>(
        xh, xl, 0, wqh, wql, 0, kv, 4096, 0, 1.f, nullptr);

    // kv -> kt (k0^T), v (copy), vt (v^T), all bf16 splits
    transpose_split_k<<<dim3(64, 64, 4), dim3(32, 8)>>>(kv,        sKV, 4096, kth, ktl, sSQ);
    copy_split_k     <<<dim3(2, 2048, 4), 256>>>      (kv + 2048, 4096, sKV, vh,  vl,  sSQ);
    transpose_split_k<<<dim3(64, 64, 4), dim3(32, 8)>>>(kv + 2048, sKV, 4096, vth, vtl, sSQ);

    // K2: s = scale * kt @ v^T (per batch)
    gemm_mma<<<dim3(16, 16, 4), 256, GEMM_SMEM>>>(
        kth, ktl, sSQ, vh, vl, sSQ, s, 2048, sSQ, scale, nullptr);

    // K3: softmax rows -> bf16 splits
    softmax_split_k<<<8192, 256>>>(s, ah, al);

    // K4: q = a @ vt^T (per batch)
    gemm_mma<<<dim3(16, 16, 4), 256, GEMM_SMEM>>>(
        ah, al, sSQ, vth, vtl, sSQ, q, 2048, sSQ, 1.f, nullptr);

    // gather + split q rows
    gather_split_k<<<dim3(2, 8192, 1), 256>>>(q, qgh, qgl);

    // K5: out = qg @ w_dense^T + bias   M=8192 N=2048 K=2048
    gemm_mma<<<dim3(16, 64, 1), 256, GEMM_SMEM>>>(
        qgh, qgl, 0, wdh, wdl, 0, out, 2048, 0, 1.f, b_dense);
}

// round 10
// speedup vs baseline: 1.4240x; 1.2388x over previous
#include <cuda_runtime.h>
#include <cuda_bf16.h>
#include <math.h>
#include <stdint.h>

// Problem: B=4, T=2048, D=2048, HEADS=16
// Chain:
//   K1: kv = x(8192x2048) @ w_qk^T(4096x2048)      -> g_kv fp32   [3 products]
//   prep: kt=k0^T (hi only), v (hi only), vt=v^T (hi+lo)
//   K2: s = scale * kt @ v^T                        -> g_s fp32   [1 product]
//   K3: row softmax of s -> bf16 hi/lo splits (a)
//   K4: q = a @ vt^T                                -> g_q fp32   [3 products]
//   prep: qg[r] = q[gather(r)] bf16 splits
//   K5: out = qg @ w_dense^T + bias                               [3 products]
//
// GEMM engine: mma.sync m16n8k16 bf16. R10: XOR-swizzled 64B rows (no pad)
// -> 32KB stages -> 3-stage single-sync cp.async ring AND 2 CTAs/SM.
// K2 runs hh-only (softmax absolute-logit insensitivity), skipping lo tiles.

// ---------------------------------------------------------------- scratch ---
static __device__ float g_kv[33554432];   // 4*2048*4096
static __device__ float g_s [16777216];   // 4*2048*2048
static __device__ float g_q [16777216];   // 4*2048*2048

static __device__ __nv_bfloat16 g_xh[16777216],  g_xl[16777216];
static __device__ __nv_bfloat16 g_wqh[8388608],  g_wql[8388608];
static __device__ __nv_bfloat16 g_wdh[4194304],  g_wdl[4194304];
static __device__ __nv_bfloat16 g_kth[16777216];                   // kt hi only
static __device__ __nv_bfloat16 g_vh [16777216];                   // v  hi only
static __device__ __nv_bfloat16 g_vth[16777216], g_vtl[16777216];
static __device__ __nv_bfloat16 g_ah [16777216], g_al [16777216];
static __device__ __nv_bfloat16 g_qgh[16777216], g_qgl[16777216];

// --------------------------------------------------------------- helpers ---
__device__ __forceinline__ uint32_t smem_u32(const void* p) {
    uint32_t a;
    asm("{ .reg .u64 t; cvta.to.shared.u64 t, %1; cvt.u32.u64 %0, t; }"
        : "=r"(a) : "l"(p));
    return a;
}
__device__ __forceinline__ void cp16(uint32_t dst, const void* src) {
    asm volatile("cp.async.cg.shared.global [%0], [%1], 16;"
                 :: "r"(dst), "l"(src) : "memory");
}
#define CP_COMMIT() asm volatile("cp.async.commit_group;" ::: "memory")
#define CP_WAIT1()  asm volatile("cp.async.wait_group 1;" ::: "memory")

__device__ __forceinline__ void ldsm4(uint32_t* r, uint32_t addr) {
    asm volatile("ldmatrix.sync.aligned.m8n8.x4.shared.b16 {%0,%1,%2,%3}, [%4];"
                 : "=r"(r[0]), "=r"(r[1]), "=r"(r[2]), "=r"(r[3]) : "r"(addr));
}
__device__ __forceinline__ void mma16816(float* c, const uint32_t* a, const uint32_t* b) {
    asm volatile(
        "mma.sync.aligned.m16n8k16.row.col.f32.bf16.bf16.f32 "
        "{%0,%1,%2,%3}, {%4,%5,%6,%7}, {%8,%9}, {%0,%1,%2,%3};"
        : "+f"(c[0]), "+f"(c[1]), "+f"(c[2]), "+f"(c[3])
        : "r"(a[0]), "r"(a[1]), "r"(a[2]), "r"(a[3]), "r"(b[0]), "r"(b[1]));
}

__device__ __forceinline__ void split1(float x, __nv_bfloat16& h, __nv_bfloat16& l) {
    h = __float2bfloat16(x);
    l = __float2bfloat16(x - __bfloat162float(h));
}
__device__ __forceinline__ size_t gather_row_off(int r) {
    int vh = r >> 6;
    int b  = (r >> 4) & 3;
    int h  = r & 15;
    return ((size_t)b * 2048 + (size_t)h * 128 + (size_t)vh) * 2048;
}

// ------------------------------------------------------------ bf16 GEMM ----
// C(m,n) = alpha*sum_k A(m,k)*B(n,k) [+bias(n)]
// NPROD==3: A=Ah+Al, B=Bh+Bl, products hh+hl+lh. NPROD==1: hh only.
// Operands K-major bf16, row length 2048, K=2048.
// Block 128x128, GBK=32, 8 warps (2x4), warp tile 64x32.
// XOR-swizzled 64B smem rows; 3-stage single-sync cp.async ring; 2 CTAs/SM.
#define GK       2048
#define GBK      32
#define NCHUNK   (GK / GBK)        // 64
#define ROWB     64u               // 32 bf16, no pad (XOR swizzle)
#define TILE_B   (128u * ROWB)     // 8192
#define OFF_AH   0u
#define OFF_AL   TILE_B
#define OFF_BH   (2u * TILE_B)
#define OFF_BL   (3u * TILE_B)
#define STAGE_B  (4u * TILE_B)     // 32768
#define GEMM_SMEM (3u * STAGE_B)   // 98304 -> 2 CTAs/SM

// swizzled in-tile offset for (row, 16B-chunk c): c' = c ^ ((row>>1)&3)
__device__ __forceinline__ uint32_t swz(uint32_t row, uint32_t c) {
    return row * ROWB + ((c ^ ((row >> 1) & 3u)) << 4);
}

template<int NPROD>
__global__ __launch_bounds__(256, 2)
void gemm_mma(const __nv_bfloat16* __restrict__ Ah, const __nv_bfloat16* __restrict__ Al,
              size_t strideA,
              const __nv_bfloat16* __restrict__ Bh, const __nv_bfloat16* __restrict__ Bl,
              size_t strideB,
              float* __restrict__ C, int ldc, size_t strideC,
              float alpha, const float* __restrict__ bias)
{
    extern __shared__ char smem[];
    const uint32_t sbase = smem_u32(smem);

    const int tid  = threadIdx.x;
    const int lane = tid & 31;
    const int wid  = tid >> 5;
    const int wm0  = (wid & 1) * 64;    // warp M offset
    const int wn0  = (wid >> 1) * 32;   // warp N offset

    Ah += blockIdx.z * strideA;
    Bh += blockIdx.z * strideB;
    if (NPROD == 3) { Al += blockIdx.z * strideA; Bl += blockIdx.z * strideB; }
    C += blockIdx.z * strideC;
    const int m0 = blockIdx.y * 128;
    const int n0 = blockIdx.x * 128;

    // loader: lc = 16B chunk 0..3, lr = row 0..63 (two row blocks)
    const int lc = tid & 3;
    const int lr = tid >> 2;

    auto load_stage = [&](int t) {
        if (t < NCHUNK) {
            const uint32_t sb = sbase + (uint32_t)(t % 3) * STAGE_B;
            const int ks = t * GBK;
#pragma unroll
            for (int i = 0; i < 2; i++) {
                const uint32_t row = (uint32_t)(lr + i * 64);
                const uint32_t d = swz(row, (uint32_t)lc);
                const size_t aoff = (size_t)(m0 + row) * GK + ks + lc * 8;
                const size_t boff = (size_t)(n0 + row) * GK + ks + lc * 8;
                cp16(sb + OFF_AH + d, Ah + aoff);
                cp16(sb + OFF_BH + d, Bh + boff);
                if (NPROD == 3) {
                    cp16(sb + OFF_AL + d, Al + aoff);
                    cp16(sb + OFF_BL + d, Bl + boff);
                }
            }
        }
        CP_COMMIT();
    };

    float acc[4][4][4];
#pragma unroll
    for (int i = 0; i < 4; i++)
#pragma unroll
        for (int j = 0; j < 4; j++)
#pragma unroll
            for (int k = 0; k < 4; k++) acc[i][j][k] = 0.f;

    // ldmatrix lane bases: swizzle xor-offsets per k16 (row-group const across mt/p)
    const uint32_t a_row = (uint32_t)(wm0 + (lane & 15));
    const uint32_t a_s   = (a_row >> 1) & 3u;
    const uint32_t a_hi  = (uint32_t)(lane >> 4);          // 0/1 -> k 0-7 / 8-15
    const uint32_t a_base = a_row * ROWB;
    const uint32_t a_x0 = ((a_hi ^ a_s) << 4);             // k16 = 0
    const uint32_t a_x1 = (((2u | a_hi) ^ a_s) << 4);      // k16 = 1

    const uint32_t b_row = (uint32_t)(wn0 + ((lane >> 4) & 1) * 8 + (lane & 7));
    const uint32_t b_s   = (b_row >> 1) & 3u;
    const uint32_t b_hi  = (uint32_t)((lane >> 3) & 1);
    const uint32_t b_base = b_row * ROWB;
    const uint32_t b_x0 = ((b_hi ^ b_s) << 4);
    const uint32_t b_x1 = (((2u | b_hi) ^ b_s) << 4);

    load_stage(0);
    load_stage(1);

    for (int t = 0; t < NCHUNK; t++) {
        CP_WAIT1();                 // stage t landed (tail commits are empty)
        __syncthreads();            // all reads of slot (t-1)%3 done
        load_stage(t + 2);          // refill slot (t+2)%3 == (t-1)%3

        const uint32_t sb = sbase + (uint32_t)(t % 3) * STAGE_B;
#pragma unroll
        for (int k16 = 0; k16 < 2; k16++) {
            const uint32_t ax = k16 ? a_x1 : a_x0;
            const uint32_t bx = k16 ? b_x1 : b_x0;
            // --- product 1: Ah * Bh ---
            uint32_t ah[4][4], bh[2][4];
#pragma unroll
            for (int mt = 0; mt < 4; mt++)
                ldsm4(ah[mt], sb + OFF_AH + a_base + (uint32_t)mt * (16u * ROWB) + ax);
#pragma unroll
            for (int p = 0; p < 2; p++)
                ldsm4(bh[p], sb + OFF_BH + b_base + (uint32_t)p * (16u * ROWB) + bx);
#pragma unroll
            for (int mt = 0; mt < 4; mt++)
#pragma unroll
                for (int p = 0; p < 2; p++) {
                    mma16816(acc[mt][2 * p + 0], ah[mt], &bh[p][0]);
                    mma16816(acc[mt][2 * p + 1], ah[mt], &bh[p][2]);
                }
            if (NPROD == 3) {
                // --- product 2: Ah * Bl (bl short-lived) ---
                {
                    uint32_t bl[2][4];
#pragma unroll
                    for (int p = 0; p < 2; p++)
                        ldsm4(bl[p], sb + OFF_BL + b_base + (uint32_t)p * (16u * ROWB) + bx);
#pragma unroll
                    for (int mt = 0; mt < 4; mt++)
#pragma unroll
                        for (int p = 0; p < 2; p++) {
                            mma16816(acc[mt][2 * p + 0], ah[mt], &bl[p][0]);
                            mma16816(acc[mt][2 * p + 1], ah[mt], &bl[p][2]);
                        }
                }
                // --- product 3: Al * Bh (al short-lived, ah dead) ---
                {
                    uint32_t al[4][4];
#pragma unroll
                    for (int mt = 0; mt < 4; mt++)
                        ldsm4(al[mt], sb + OFF_AL + a_base + (uint32_t)mt * (16u * ROWB) + ax);
#pragma unroll
                    for (int mt = 0; mt < 4; mt++)
#pragma unroll
                        for (int p = 0; p < 2; p++) {
                            mma16816(acc[mt][2 * p + 0], al[mt], &bh[p][0]);
                            mma16816(acc[mt][2 * p + 1], al[mt], &bh[p][2]);
                        }
                }
            }
        }
    }

    // ---- epilogue ----
    const int er = lane >> 2;
    const int ec = (lane & 3) * 2;
#pragma unroll
    for (int mt = 0; mt < 4; mt++) {
#pragma unroll
        for (int nt = 0; nt < 4; nt++) {
            int m = m0 + wm0 + mt * 16 + er;
            int n = n0 + wn0 + nt * 8 + ec;
            float b0 = 0.f, b1 = 0.f;
            if (bias) { b0 = __ldg(bias + n); b1 = __ldg(bias + n + 1); }
            float2 v0, v1;
            v0.x = alpha * acc[mt][nt][0] + b0;
            v0.y = alpha * acc[mt][nt][1] + b1;
            v1.x = alpha * acc[mt][nt][2] + b0;
            v1.y = alpha * acc[mt][nt][3] + b1;
            *(float2*)&C[(size_t)m * (size_t)ldc + n]       = v0;
            *(float2*)&C[(size_t)(m + 8) * (size_t)ldc + n] = v1;
        }
    }
}

// ----------------------------------------------------------- prep kernels ---
__global__ __launch_bounds__(256)
void copy_split_k(const float* __restrict__ src, size_t src_rstride, size_t src_bstride,
                  __nv_bfloat16* __restrict__ dh, __nv_bfloat16* __restrict__ dl,
                  size_t dst_bstride)
{
    size_t row = blockIdx.y;
    size_t col = (size_t)blockIdx.x * 1024 + threadIdx.x * 4;
    float4 v = *(const float4*)(src + (size_t)blockIdx.z * src_bstride + row * src_rstride + col);
    __nv_bfloat16 h0, h1, h2, h3, l0, l1, l2, l3;
    split1(v.x, h0, l0); split1(v.y, h1, l1);
    split1(v.z, h2, l2); split1(v.w, h3, l3);
    size_t o = (size_t)blockIdx.z * dst_bstride + row * 2048 + col;
    ((__nv_bfloat162*)(dh + o))[0] = __halves2bfloat162(h0, h1);
    ((__nv_bfloat162*)(dh + o))[1] = __halves2bfloat162(h2, h3);
    if (dl) {
        ((__nv_bfloat162*)(dl + o))[0] = __halves2bfloat162(l0, l1);
        ((__nv_bfloat162*)(dl + o))[1] = __halves2bfloat162(l2, l3);
    }
}

__global__ __launch_bounds__(256)
void transpose_split_k(const float* __restrict__ src, size_t src_bstride, int src_ld,
                       __nv_bfloat16* __restrict__ dh, __nv_bfloat16* __restrict__ dl,
                       size_t dst_bstride)
{
    __shared__ float tile[32][33];
    int tx = threadIdx.x, ty = threadIdx.y;      // blockDim (32, 8)
    int i0 = blockIdx.x * 32, m0 = blockIdx.y * 32;
    const float* s = src + (size_t)blockIdx.z * src_bstride;
#pragma unroll
    for (int r = 0; r < 4; r++)
        tile[ty + r * 8][tx] = s[(size_t)(m0 + ty + r * 8) * src_ld + i0 + tx];
    __syncthreads();
#pragma unroll
    for (int r = 0; r < 4; r++) {
        float x = tile[tx][ty + r * 8];
        __nv_bfloat16 h, l; split1(x, h, l);
        size_t o = (size_t)blockIdx.z * dst_bstride +
                   (size_t)(i0 + ty + r * 8) * 2048 + m0 + tx;
        dh[o] = h;
        if (dl) dl[o] = l;
    }
}

__global__ __launch_bounds__(256)
void softmax_split_k(const float* __restrict__ s,
                     __nv_bfloat16* __restrict__ ah, __nv_bfloat16* __restrict__ al)
{
    const float* p = s + (size_t)blockIdx.x * 2048;
    int tid = threadIdx.x, warp = tid >> 5, lane = tid & 31;
    __shared__ float red[8];

    float4 v0 = *(const float4*)(p + tid * 4);
    float4 v1 = *(const float4*)(p + 1024 + tid * 4);

    float m = fmaxf(fmaxf(fmaxf(v0.x, v0.y), fmaxf(v0.z, v0.w)),
                    fmaxf(fmaxf(v1.x, v1.y), fmaxf(v1.z, v1.w)));
#pragma unroll
    for (int o = 16; o > 0; o >>= 1) m = fmaxf(m, __shfl_xor_sync(0xffffffffu, m, o));
    if (lane == 0) red[warp] = m;
    __syncthreads();
    float bm = red[0];
#pragma unroll
    for (int i = 1; i < 8; i++) bm = fmaxf(bm, red[i]);
    __syncthreads();

    v0.x = __expf(v0.x - bm); v0.y = __expf(v0.y - bm);
    v0.z = __expf(v0.z - bm); v0.w = __expf(v0.w - bm);
    v1.x = __expf(v1.x - bm); v1.y = __expf(v1.y - bm);
    v1.z = __expf(v1.z - bm); v1.w = __expf(v1.w - bm);

    float sm = v0.x + v0.y + v0.z + v0.w + v1.x + v1.y + v1.z + v1.w;
#pragma unroll
    for (int o = 16; o > 0; o >>= 1) sm += __shfl_xor_sync(0xffffffffu, sm, o);
    if (lane == 0) red[warp] = sm;
    __syncthreads();
    float tot = red[0];
#pragma unroll
    for (int i = 1; i < 8; i++) tot += red[i];
    float inv = 1.f / tot;

    size_t base = (size_t)blockIdx.x * 2048;
    float vals[8] = {v0.x * inv, v0.y * inv, v0.z * inv, v0.w * inv,
                     v1.x * inv, v1.y * inv, v1.z * inv, v1.w * inv};
    size_t offs[2] = {base + tid * 4, base + 1024 + tid * 4};
#pragma unroll
    for (int half = 0; half < 2; half++) {
        __nv_bfloat16 h0, h1, h2, h3, l0, l1, l2, l3;
        split1(vals[half * 4 + 0], h0, l0); split1(vals[half * 4 + 1], h1, l1);
        split1(vals[half * 4 + 2], h2, l2); split1(vals[half * 4 + 3], h3, l3);
        size_t o = offs[half];
        ((__nv_bfloat162*)(ah + o))[0] = __halves2bfloat162(h0, h1);
        ((__nv_bfloat162*)(ah + o))[1] = __halves2bfloat162(h2, h3);
        ((__nv_bfloat162*)(al + o))[0] = __halves2bfloat162(l0, l1);
        ((__nv_bfloat162*)(al + o))[1] = __halves2bfloat162(l2, l3);
    }
}

__global__ __launch_bounds__(256)
void gather_split_k(const float* __restrict__ q,
                    __nv_bfloat16* __restrict__ dh, __nv_bfloat16* __restrict__ dl)
{
    int r = blockIdx.y;
    size_t col = (size_t)blockIdx.x * 1024 + threadIdx.x * 4;
    float4 v = *(const float4*)(q + gather_row_off(r) + col);
    __nv_bfloat16 h0, h1, h2, h3, l0, l1, l2, l3;
    split1(v.x, h0, l0); split1(v.y, h1, l1);
    split1(v.z, h2, l2); split1(v.w, h3, l3);
    size_t o = (size_t)r * 2048 + col;
    ((__nv_bfloat162*)(dh + o))[0] = __halves2bfloat162(h0, h1);
    ((__nv_bfloat162*)(dh + o))[1] = __halves2bfloat162(h2, h3);
    ((__nv_bfloat162*)(dl + o))[0] = __halves2bfloat162(l0, l1);
    ((__nv_bfloat162*)(dl + o))[1] = __halves2bfloat162(l2, l3);
}

// ------------------------------------------------------------------ driver ---
extern "C" void kernel_launch(void* const* d_in, const int* in_sizes, int n_in,
                              void* d_out, int out_size)
{
    const float* x       = (const float*)d_in[0];
    const float* w_qk    = (const float*)d_in[1];
    const float* w_dense = (const float*)d_in[2];
    const float* b_dense = (const float*)d_in[3];
    float* out = (float*)d_out;

    float *kv, *s, *q;
    cudaGetSymbolAddress((void**)&kv, g_kv);
    cudaGetSymbolAddress((void**)&s,  g_s);
    cudaGetSymbolAddress((void**)&q,  g_q);
    __nv_bfloat16 *xh, *xl, *wqh, *wql, *wdh, *wdl, *kth, *vh,
                  *vth, *vtl, *ah, *al, *qgh, *qgl;
    cudaGetSymbolAddress((void**)&xh,  g_xh);  cudaGetSymbolAddress((void**)&xl,  g_xl);
    cudaGetSymbolAddress((void**)&wqh, g_wqh); cudaGetSymbolAddress((void**)&wql, g_wql);
    cudaGetSymbolAddress((void**)&wdh, g_wdh); cudaGetSymbolAddress((void**)&wdl, g_wdl);
    cudaGetSymbolAddress((void**)&kth, g_kth);
    cudaGetSymbolAddress((void**)&vh,  g_vh);
    cudaGetSymbolAddress((void**)&vth, g_vth); cudaGetSymbolAddress((void**)&vtl, g_vtl);
    cudaGetSymbolAddress((void**)&ah,  g_ah);  cudaGetSymbolAddress((void**)&al,  g_al);
    cudaGetSymbolAddress((void**)&qgh, g_qgh); cudaGetSymbolAddress((void**)&qgl, g_qgl);

    cudaFuncSetAttribute(gemm_mma<3>, cudaFuncAttributeMaxDynamicSharedMemorySize, GEMM_SMEM);
    cudaFuncSetAttribute(gemm_mma<1>, cudaFuncAttributeMaxDynamicSharedMemorySize, GEMM_SMEM);

    const float scale = (float)(1.0 / sqrt(2048.0 * 2047.0 / 2.0));
    const size_t sKV = 2048ull * 4096ull;
    const size_t sSQ = 2048ull * 2048ull;

    // splits of the raw inputs
    copy_split_k<<<dim3(2, 8192, 1), 256>>>(x,       2048, 0, xh,  xl,  0);
    copy_split_k<<<dim3(2, 4096, 1), 256>>>(w_qk,    2048, 0, wqh, wql, 0);
    copy_split_k<<<dim3(2, 2048, 1), 256>>>(w_dense, 2048, 0, wdh, wdl, 0);

    // K1: kv = x @ w_qk^T   M=8192 N=4096 K=2048
    gemm_mma<3><<<dim3(32, 64, 1), 256, GEMM_SMEM>>>(
        xh, xl, 0, wqh, wql, 0, kv, 4096, 0, 1.f, nullptr);

    // kv -> kt (hi only), v (hi only), vt (hi+lo)
    transpose_split_k<<<dim3(64, 64, 4), dim3(32, 8)>>>(kv,        sKV, 4096, kth, nullptr, sSQ);
    copy_split_k     <<<dim3(2, 2048, 4), 256>>>      (kv + 2048, 4096, sKV, vh,  nullptr, sSQ);
    transpose_split_k<<<dim3(64, 64, 4), dim3(32, 8)>>>(kv + 2048, sKV, 4096, vth, vtl,    sSQ);

    // K2: s = scale * kt @ v^T (per batch) — single product (softmax-insensitive)
    gemm_mma<1><<<dim3(16, 16, 4), 256, GEMM_SMEM>>>(
        kth, nullptr, sSQ, vh, nullptr, sSQ, s, 2048, sSQ, scale, nullptr);

    // K3: softmax rows -> bf16 splits
    softmax_split_k<<<8192, 256>>>(s, ah, al);

    // K4: q = a @ vt^T (per batch)
    gemm_mma<3><<<dim3(16, 16, 4), 256, GEMM_SMEM>>>(
        ah, al, sSQ, vth, vtl, sSQ, q, 2048, sSQ, 1.f, nullptr);

    // gather + split q rows
    gather_split_k<<<dim3(2, 8192, 1), 256>>>(q, qgh, qgl);

    // K5: out = qg @ w_dense^T + bias   M=8192 N=2048 K=2048
    gemm_mma<3><<<dim3(16, 64, 1), 256, GEMM_SMEM>>>(
        qgh, qgl, 0, wdh, wdl, 0, out, 2048, 0, 1.f, b_dense);
}

// round 11
// speedup vs baseline: 1.6509x; 1.1593x over previous
#include <cuda_runtime.h>
#include <cuda_bf16.h>
#include <math.h>
#include <stdint.h>

// Problem: B=4, T=2048, D=2048, HEADS=16
// Chain:
//   K1a: kv[:, 0:2048]    = x @ w_qk[0:2048]^T     [1 product]  (k0: softmax-insensitive)
//   K1b: kv[:, 2048:4096] = x @ w_qk[2048:]^T      [3 products] (v: full precision)
//   prep: kt=k0^T (hi), v (hi), vt=v^T (hi+lo)
//   K2: s = scale * kt @ v^T                        [1 product]
//   K3: row softmax of s -> bf16 hi/lo splits (a)
//   K4: q = a @ vt^T, epilogue writes gathered bf16 splits qg directly [3 products]
//   K5: out = qg @ w_dense^T + bias                 [3 products]
//
// GEMM engine: mma.sync m16n8k16 bf16, XOR-swizzled 64B smem rows,
// 3-stage single-sync cp.async ring, 2 CTAs/SM.

// ---------------------------------------------------------------- scratch ---
static __device__ float g_kv[33554432];   // 4*2048*4096
static __device__ float g_s [16777216];   // 4*2048*2048

static __device__ __nv_bfloat16 g_xh[16777216],  g_xl[16777216];
static __device__ __nv_bfloat16 g_wqh[8388608],  g_wql[8388608];
static __device__ __nv_bfloat16 g_wdh[4194304],  g_wdl[4194304];
static __device__ __nv_bfloat16 g_kth[16777216];                   // kt hi only
static __device__ __nv_bfloat16 g_vh [16777216];                   // v  hi only
static __device__ __nv_bfloat16 g_vth[16777216], g_vtl[16777216];
static __device__ __nv_bfloat16 g_ah [16777216], g_al [16777216];
static __device__ __nv_bfloat16 g_qgh[16777216], g_qgl[16777216];

// --------------------------------------------------------------- helpers ---
__device__ __forceinline__ uint32_t smem_u32(const void* p) {
    uint32_t a;
    asm("{ .reg .u64 t; cvta.to.shared.u64 t, %1; cvt.u32.u64 %0, t; }"
        : "=r"(a) : "l"(p));
    return a;
}
__device__ __forceinline__ void cp16(uint32_t dst, const void* src) {
    asm volatile("cp.async.cg.shared.global [%0], [%1], 16;"
                 :: "r"(dst), "l"(src) : "memory");
}
#define CP_COMMIT() asm volatile("cp.async.commit_group;" ::: "memory")
#define CP_WAIT1()  asm volatile("cp.async.wait_group 1;" ::: "memory")

__device__ __forceinline__ void ldsm4(uint32_t* r, uint32_t addr) {
    asm volatile("ldmatrix.sync.aligned.m8n8.x4.shared.b16 {%0,%1,%2,%3}, [%4];"
                 : "=r"(r[0]), "=r"(r[1]), "=r"(r[2]), "=r"(r[3]) : "r"(addr));
}
__device__ __forceinline__ void mma16816(float* c, const uint32_t* a, const uint32_t* b) {
    asm volatile(
        "mma.sync.aligned.m16n8k16.row.col.f32.bf16.bf16.f32 "
        "{%0,%1,%2,%3}, {%4,%5,%6,%7}, {%8,%9}, {%0,%1,%2,%3};"
        : "+f"(c[0]), "+f"(c[1]), "+f"(c[2]), "+f"(c[3])
        : "r"(a[0]), "r"(a[1]), "r"(a[2]), "r"(a[3]), "r"(b[0]), "r"(b[1]));
}

__device__ __forceinline__ void split1(float x, __nv_bfloat16& h, __nv_bfloat16& l) {
    h = __float2bfloat16(x);
    l = __float2bfloat16(x - __bfloat162float(h));
}

// ------------------------------------------------------------ bf16 GEMM ----
// C(m,n) = alpha*sum_k A(m,k)*B(n,k) [+bias(n)]
// NPROD==3: hh+hl+lh.  NPROD==1: hh only (skips lo tiles entirely).
// GEPI==1: instead of fp32 C, write bf16 hi/lo splits to gh/gl at gathered
//          row r = (m&127)*64 + blockIdx.z*16 + (m>>7)  (the head permutation).
// Operands K-major bf16, row length 2048, K=2048. Block 128x128, GBK=32,
// 8 warps (2x4), warp tile 64x32, XOR swizzle, 3-stage ring, 2 CTAs/SM.
#define GK       2048
#define GBK      32
#define NCHUNK   (GK / GBK)        // 64
#define ROWB     64u
#define TILE_B   (128u * ROWB)     // 8192
#define OFF_AH   0u
#define OFF_AL   TILE_B
#define OFF_BH   (2u * TILE_B)
#define OFF_BL   (3u * TILE_B)
#define STAGE_B  (4u * TILE_B)     // 32768
#define GEMM_SMEM (3u * STAGE_B)   // 98304 -> 2 CTAs/SM

__device__ __forceinline__ uint32_t swz(uint32_t row, uint32_t c) {
    return row * ROWB + ((c ^ ((row >> 1) & 3u)) << 4);
}

template<int NPROD, int GEPI>
__global__ __launch_bounds__(256, 2)
void gemm_mma(const __nv_bfloat16* __restrict__ Ah, const __nv_bfloat16* __restrict__ Al,
              size_t strideA,
              const __nv_bfloat16* __restrict__ Bh, const __nv_bfloat16* __restrict__ Bl,
              size_t strideB,
              float* __restrict__ C, int ldc, size_t strideC,
              float alpha, const float* __restrict__ bias,
              __nv_bfloat16* __restrict__ gh, __nv_bfloat16* __restrict__ gl)
{
    extern __shared__ char smem[];
    const uint32_t sbase = smem_u32(smem);

    const int tid  = threadIdx.x;
    const int lane = tid & 31;
    const int wid  = tid >> 5;
    const int wm0  = (wid & 1) * 64;
    const int wn0  = (wid >> 1) * 32;

    Ah += blockIdx.z * strideA;
    Bh += blockIdx.z * strideB;
    if (NPROD == 3) { Al += blockIdx.z * strideA; Bl += blockIdx.z * strideB; }
    if (!GEPI) C += blockIdx.z * strideC;
    const int m0 = blockIdx.y * 128;
    const int n0 = blockIdx.x * 128;

    const int lc = tid & 3;
    const int lr = tid >> 2;

    auto load_stage = [&](int t) {
        if (t < NCHUNK) {
            const uint32_t sb = sbase + (uint32_t)(t % 3) * STAGE_B;
            const int ks = t * GBK;
#pragma unroll
            for (int i = 0; i < 2; i++) {
                const uint32_t row = (uint32_t)(lr + i * 64);
                const uint32_t d = swz(row, (uint32_t)lc);
                const size_t aoff = (size_t)(m0 + row) * GK + ks + lc * 8;
                const size_t boff = (size_t)(n0 + row) * GK + ks + lc * 8;
                cp16(sb + OFF_AH + d, Ah + aoff);
                cp16(sb + OFF_BH + d, Bh + boff);
                if (NPROD == 3) {
                    cp16(sb + OFF_AL + d, Al + aoff);
                    cp16(sb + OFF_BL + d, Bl + boff);
                }
            }
        }
        CP_COMMIT();
    };

    float acc[4][4][4];
#pragma unroll
    for (int i = 0; i < 4; i++)
#pragma unroll
        for (int j = 0; j < 4; j++)
#pragma unroll
            for (int k = 0; k < 4; k++) acc[i][j][k] = 0.f;

    const uint32_t a_row = (uint32_t)(wm0 + (lane & 15));
    const uint32_t a_s   = (a_row >> 1) & 3u;
    const uint32_t a_hi  = (uint32_t)(lane >> 4);
    const uint32_t a_base = a_row * ROWB;
    const uint32_t a_x0 = ((a_hi ^ a_s) << 4);
    const uint32_t a_x1 = (((2u | a_hi) ^ a_s) << 4);

    const uint32_t b_row = (uint32_t)(wn0 + ((lane >> 4) & 1) * 8 + (lane & 7));
    const uint32_t b_s   = (b_row >> 1) & 3u;
    const uint32_t b_hi  = (uint32_t)((lane >> 3) & 1);
    const uint32_t b_base = b_row * ROWB;
    const uint32_t b_x0 = ((b_hi ^ b_s) << 4);
    const uint32_t b_x1 = (((2u | b_hi) ^ b_s) << 4);

    load_stage(0);
    load_stage(1);

    for (int t = 0; t < NCHUNK; t++) {
        CP_WAIT1();
        __syncthreads();
        load_stage(t + 2);

        const uint32_t sb = sbase + (uint32_t)(t % 3) * STAGE_B;
#pragma unroll
        for (int k16 = 0; k16 < 2; k16++) {
            const uint32_t ax = k16 ? a_x1 : a_x0;
            const uint32_t bx = k16 ? b_x1 : b_x0;
            uint32_t ah[4][4], bh[2][4];
#pragma unroll
            for (int mt = 0; mt < 4; mt++)
                ldsm4(ah[mt], sb + OFF_AH + a_base + (uint32_t)mt * (16u * ROWB) + ax);
#pragma unroll
            for (int p = 0; p < 2; p++)
                ldsm4(bh[p], sb + OFF_BH + b_base + (uint32_t)p * (16u * ROWB) + bx);
#pragma unroll
            for (int mt = 0; mt < 4; mt++)
#pragma unroll
                for (int p = 0; p < 2; p++) {
                    mma16816(acc[mt][2 * p + 0], ah[mt], &bh[p][0]);
                    mma16816(acc[mt][2 * p + 1], ah[mt], &bh[p][2]);
                }
            if (NPROD == 3) {
                {
                    uint32_t bl[2][4];
#pragma unroll
                    for (int p = 0; p < 2; p++)
                        ldsm4(bl[p], sb + OFF_BL + b_base + (uint32_t)p * (16u * ROWB) + bx);
#pragma unroll
                    for (int mt = 0; mt < 4; mt++)
#pragma unroll
                        for (int p = 0; p < 2; p++) {
                            mma16816(acc[mt][2 * p + 0], ah[mt], &bl[p][0]);
                            mma16816(acc[mt][2 * p + 1], ah[mt], &bl[p][2]);
                        }
                }
                {
                    uint32_t al[4][4];
#pragma unroll
                    for (int mt = 0; mt < 4; mt++)
                        ldsm4(al[mt], sb + OFF_AL + a_base + (uint32_t)mt * (16u * ROWB) + ax);
#pragma unroll
                    for (int mt = 0; mt < 4; mt++)
#pragma unroll
                        for (int p = 0; p < 2; p++) {
                            mma16816(acc[mt][2 * p + 0], al[mt], &bh[p][0]);
                            mma16816(acc[mt][2 * p + 1], al[mt], &bh[p][2]);
                        }
                }
            }
        }
    }

    // ---- epilogue ----
    const int er = lane >> 2;
    const int ec = (lane & 3) * 2;
#pragma unroll
    for (int mt = 0; mt < 4; mt++) {
#pragma unroll
        for (int nt = 0; nt < 4; nt++) {
            int m = m0 + wm0 + mt * 16 + er;
            int n = n0 + wn0 + nt * 8 + ec;
            if (GEPI) {
                // gathered bf16-split write: q row m of batch z -> out row r
                int b  = (int)blockIdx.z;
                int r1 = ((m & 127) << 6) + b * 16 + (m >> 7);
                int m2 = m + 8;
                int r2 = ((m2 & 127) << 6) + b * 16 + (m2 >> 7);
                __nv_bfloat16 h0, l0, h1, l1;
                split1(acc[mt][nt][0], h0, l0);
                split1(acc[mt][nt][1], h1, l1);
                *(__nv_bfloat162*)(gh + (size_t)r1 * 2048 + n) = __halves2bfloat162(h0, h1);
                *(__nv_bfloat162*)(gl + (size_t)r1 * 2048 + n) = __halves2bfloat162(l0, l1);
                split1(acc[mt][nt][2], h0, l0);
                split1(acc[mt][nt][3], h1, l1);
                *(__nv_bfloat162*)(gh + (size_t)r2 * 2048 + n) = __halves2bfloat162(h0, h1);
                *(__nv_bfloat162*)(gl + (size_t)r2 * 2048 + n) = __halves2bfloat162(l0, l1);
            } else {
                float b0 = 0.f, b1 = 0.f;
                if (bias) { b0 = __ldg(bias + n); b1 = __ldg(bias + n + 1); }
                float2 v0, v1;
                v0.x = alpha * acc[mt][nt][0] + b0;
                v0.y = alpha * acc[mt][nt][1] + b1;
                v1.x = alpha * acc[mt][nt][2] + b0;
                v1.y = alpha * acc[mt][nt][3] + b1;
                *(float2*)&C[(size_t)m * (size_t)ldc + n]       = v0;
                *(float2*)&C[(size_t)(m + 8) * (size_t)ldc + n] = v1;
            }
        }
    }
}

// ----------------------------------------------------------- prep kernels ---
__global__ __launch_bounds__(256)
void copy_split_k(const float* __restrict__ src, size_t src_rstride, size_t src_bstride,
                  __nv_bfloat16* __restrict__ dh, __nv_bfloat16* __restrict__ dl,
                  size_t dst_bstride)
{
    size_t row = blockIdx.y;
    size_t col = (size_t)blockIdx.x * 1024 + threadIdx.x * 4;
    float4 v = *(const float4*)(src + (size_t)blockIdx.z * src_bstride + row * src_rstride + col);
    __nv_bfloat16 h0, h1, h2, h3, l0, l1, l2, l3;
    split1(v.x, h0, l0); split1(v.y, h1, l1);
    split1(v.z, h2, l2); split1(v.w, h3, l3);
    size_t o = (size_t)blockIdx.z * dst_bstride + row * 2048 + col;
    ((__nv_bfloat162*)(dh + o))[0] = __halves2bfloat162(h0, h1);
    ((__nv_bfloat162*)(dh + o))[1] = __halves2bfloat162(h2, h3);
    if (dl) {
        ((__nv_bfloat162*)(dl + o))[0] = __halves2bfloat162(l0, l1);
        ((__nv_bfloat162*)(dl + o))[1] = __halves2bfloat162(l2, l3);
    }
}

__global__ __launch_bounds__(256)
void transpose_split_k(const float* __restrict__ src, size_t src_bstride, int src_ld,
                       __nv_bfloat16* __restrict__ dh, __nv_bfloat16* __restrict__ dl,
                       size_t dst_bstride)
{
    __shared__ float tile[32][33];
    int tx = threadIdx.x, ty = threadIdx.y;      // blockDim (32, 8)
    int i0 = blockIdx.x * 32, m0 = blockIdx.y * 32;
    const float* s = src + (size_t)blockIdx.z * src_bstride;
#pragma unroll
    for (int r = 0; r < 4; r++)
        tile[ty + r * 8][tx] = s[(size_t)(m0 + ty + r * 8) * src_ld + i0 + tx];
    __syncthreads();
#pragma unroll
    for (int r = 0; r < 4; r++) {
        float x = tile[tx][ty + r * 8];
        __nv_bfloat16 h, l; split1(x, h, l);
        size_t o = (size_t)blockIdx.z * dst_bstride +
                   (size_t)(i0 + ty + r * 8) * 2048 + m0 + tx;
        dh[o] = h;
        if (dl) dl[o] = l;
    }
}

__global__ __launch_bounds__(256)
void softmax_split_k(const float* __restrict__ s,
                     __nv_bfloat16* __restrict__ ah, __nv_bfloat16* __restrict__ al)
{
    const float* p = s + (size_t)blockIdx.x * 2048;
    int tid = threadIdx.x, warp = tid >> 5, lane = tid & 31;
    __shared__ float red[8];

    float4 v0 = *(const float4*)(p + tid * 4);
    float4 v1 = *(const float4*)(p + 1024 + tid * 4);

    float m = fmaxf(fmaxf(fmaxf(v0.x, v0.y), fmaxf(v0.z, v0.w)),
                    fmaxf(fmaxf(v1.x, v1.y), fmaxf(v1.z, v1.w)));
#pragma unroll
    for (int o = 16; o > 0; o >>= 1) m = fmaxf(m, __shfl_xor_sync(0xffffffffu, m, o));
    if (lane == 0) red[warp] = m;
    __syncthreads();
    float bm = red[0];
#pragma unroll
    for (int i = 1; i < 8; i++) bm = fmaxf(bm, red[i]);
    __syncthreads();

    v0.x = __expf(v0.x - bm); v0.y = __expf(v0.y - bm);
    v0.z = __expf(v0.z - bm); v0.w = __expf(v0.w - bm);
    v1.x = __expf(v1.x - bm); v1.y = __expf(v1.y - bm);
    v1.z = __expf(v1.z - bm); v1.w = __expf(v1.w - bm);

    float sm = v0.x + v0.y + v0.z + v0.w + v1.x + v1.y + v1.z + v1.w;
#pragma unroll
    for (int o = 16; o > 0; o >>= 1) sm += __shfl_xor_sync(0xffffffffu, sm, o);
    if (lane == 0) red[warp] = sm;
    __syncthreads();
    float tot = red[0];
#pragma unroll
    for (int i = 1; i < 8; i++) tot += red[i];
    float inv = 1.f / tot;

    size_t base = (size_t)blockIdx.x * 2048;
    float vals[8] = {v0.x * inv, v0.y * inv, v0.z * inv, v0.w * inv,
                     v1.x * inv, v1.y * inv, v1.z * inv, v1.w * inv};
    size_t offs[2] = {base + tid * 4, base + 1024 + tid * 4};
#pragma unroll
    for (int half = 0; half < 2; half++) {
        __nv_bfloat16 h0, h1, h2, h3, l0, l1, l2, l3;
        split1(vals[half * 4 + 0], h0, l0); split1(vals[half * 4 + 1], h1, l1);
        split1(vals[half * 4 + 2], h2, l2); split1(vals[half * 4 + 3], h3, l3);
        size_t o = offs[half];
        ((__nv_bfloat162*)(ah + o))[0] = __halves2bfloat162(h0, h1);
        ((__nv_bfloat162*)(ah + o))[1] = __halves2bfloat162(h2, h3);
        ((__nv_bfloat162*)(al + o))[0] = __halves2bfloat162(l0, l1);
        ((__nv_bfloat162*)(al + o))[1] = __halves2bfloat162(l2, l3);
    }
}

// ------------------------------------------------------------------ driver ---
extern "C" void kernel_launch(void* const* d_in, const int* in_sizes, int n_in,
                              void* d_out, int out_size)
{
    const float* x       = (const float*)d_in[0];
    const float* w_qk    = (const float*)d_in[1];
    const float* w_dense = (const float*)d_in[2];
    const float* b_dense = (const float*)d_in[3];
    float* out = (float*)d_out;

    float *kv, *s;
    cudaGetSymbolAddress((void**)&kv, g_kv);
    cudaGetSymbolAddress((void**)&s,  g_s);
    __nv_bfloat16 *xh, *xl, *wqh, *wql, *wdh, *wdl, *kth, *vh,
                  *vth, *vtl, *ah, *al, *qgh, *qgl;
    cudaGetSymbolAddress((void**)&xh,  g_xh);  cudaGetSymbolAddress((void**)&xl,  g_xl);
    cudaGetSymbolAddress((void**)&wqh, g_wqh); cudaGetSymbolAddress((void**)&wql, g_wql);
    cudaGetSymbolAddress((void**)&wdh, g_wdh); cudaGetSymbolAddress((void**)&wdl, g_wdl);
    cudaGetSymbolAddress((void**)&kth, g_kth);
    cudaGetSymbolAddress((void**)&vh,  g_vh);
    cudaGetSymbolAddress((void**)&vth, g_vth); cudaGetSymbolAddress((void**)&vtl, g_vtl);
    cudaGetSymbolAddress((void**)&ah,  g_ah);  cudaGetSymbolAddress((void**)&al,  g_al);
    cudaGetSymbolAddress((void**)&qgh, g_qgh); cudaGetSymbolAddress((void**)&qgl, g_qgl);

    cudaFuncSetAttribute(gemm_mma<3,0>, cudaFuncAttributeMaxDynamicSharedMemorySize, GEMM_SMEM);
    cudaFuncSetAttribute(gemm_mma<1,0>, cudaFuncAttributeMaxDynamicSharedMemorySize, GEMM_SMEM);
    cudaFuncSetAttribute(gemm_mma<3,1>, cudaFuncAttributeMaxDynamicSharedMemorySize, GEMM_SMEM);

    const float scale = (float)(1.0 / sqrt(2048.0 * 2047.0 / 2.0));
    const size_t sKV = 2048ull * 4096ull;
    const size_t sSQ = 2048ull * 2048ull;

    // splits of the raw inputs
    copy_split_k<<<dim3(2, 8192, 1), 256>>>(x,       2048, 0, xh,  xl,  0);
    copy_split_k<<<dim3(2, 4096, 1), 256>>>(w_qk,    2048, 0, wqh, wql, 0);
    copy_split_k<<<dim3(2, 2048, 1), 256>>>(w_dense, 2048, 0, wdh, wdl, 0);

    // K1a: k0 half (cols 0..2047) — 1 product (only feeds softmax logits)
    gemm_mma<1,0><<<dim3(16, 64, 1), 256, GEMM_SMEM>>>(
        xh, nullptr, 0, wqh, nullptr, 0, kv, 4096, 0, 1.f, nullptr, nullptr, nullptr);

    // K1b: v half (cols 2048..4095) — full 3 products
    gemm_mma<3,0><<<dim3(16, 64, 1), 256, GEMM_SMEM>>>(
        xh, xl, 0, wqh + 2048ull * 2048ull, wql + 2048ull * 2048ull, 0,
        kv + 2048, 4096, 0, 1.f, nullptr, nullptr, nullptr);

    // kv -> kt (hi only), v (hi only), vt (hi+lo)
    transpose_split_k<<<dim3(64, 64, 4), dim3(32, 8)>>>(kv,        sKV, 4096, kth, nullptr, sSQ);
    copy_split_k     <<<dim3(2, 2048, 4), 256>>>      (kv + 2048, 4096, sKV, vh,  nullptr, sSQ);
    transpose_split_k<<<dim3(64, 64, 4), dim3(32, 8)>>>(kv + 2048, sKV, 4096, vth, vtl,    sSQ);

    // K2: s = scale * kt @ v^T (per batch) — single product
    gemm_mma<1,0><<<dim3(16, 16, 4), 256, GEMM_SMEM>>>(
        kth, nullptr, sSQ, vh, nullptr, sSQ, s, 2048, sSQ, scale, nullptr, nullptr, nullptr);

    // K3: softmax rows -> bf16 splits
    softmax_split_k<<<8192, 256>>>(s, ah, al);

    // K4: q = a @ vt^T; epilogue writes gathered bf16 splits directly
    gemm_mma<3,1><<<dim3(16, 16, 4), 256, GEMM_SMEM>>>(
        ah, al, sSQ, vth, vtl, sSQ, nullptr, 0, 0, 1.f, nullptr, qgh, qgl);

    // K5: out = qg @ w_dense^T + bias   M=8192 N=2048 K=2048
    gemm_mma<3,0><<<dim3(16, 64, 1), 256, GEMM_SMEM>>>(
        qgh, qgl, 0, wdh, wdl, 0, out, 2048, 0, 1.f, b_dense, nullptr, nullptr);
}